// round 7
// baseline (speedup 1.0000x reference)
#include <cuda_runtime.h>

#define BATCH 16
typedef unsigned long long u64;

// ---------------- scratch (no allocations allowed) ----------------
__device__ float g_bufA[BATCH * 64 * 1024];
__device__ float g_bufB[BATCH * 64 * 1024];
__device__ float g_e2[512];

// ---------------- packed f32x2 helpers ----------------
__device__ __forceinline__ void ffma2(u64& d, u64 a, u64 b) {
  asm("fma.rn.f32x2 %0, %1, %2, %0;" : "+l"(d) : "l"(a), "l"(b));
}
__device__ __forceinline__ u64 bcast2(float x) {
  u64 r; asm("mov.b64 %0, {%1, %1};" : "=l"(r) : "f"(x)); return r;
}
__device__ __forceinline__ u64 pack2(float x, float y) {
  u64 r; asm("mov.b64 %0, {%1, %2};" : "=l"(r) : "f"(x), "f"(y)); return r;
}
__device__ __forceinline__ float2 unpack2(u64 v) {
  float2 f; asm("mov.b64 {%0, %1}, %2;" : "=f"(f.x), "=f"(f.y) : "l"(v)); return f;
}

// =====================================================================
// conv1: x(16,768,4096) -> (16,32,2048), k4 s2 p1, bias, ReLU
// grid (32,16) block 256.  tile 32o x 64t, c-chunks of 16.
// =====================================================================
__global__ void __launch_bounds__(256) k_conv1(
    const float* __restrict__ x, const float* __restrict__ w,
    const float* __restrict__ bias, float* __restrict__ out) {
  __shared__ __align__(16) float xs[16 * 132];   // 130 valid
  __shared__ __align__(16) float ws[64 * 32];    // [(c*4+k)][o]
  const int b   = blockIdx.y;
  const int T0  = blockIdx.x * 64;
  const int tid = threadIdx.x;
  const int og  = tid & 7;    // 8 groups x 4 o (2 packed pairs)
  const int tg  = tid >> 3;   // 32 groups, t = tg + 32j
  const int l0  = 2 * T0 - 1;

  u64 acc[2][2] = {{0ull, 0ull}, {0ull, 0ull}};

  for (int c0 = 0; c0 < 768; c0 += 16) {
    __syncthreads();
    for (int idx = tid; idx < 16 * 130; idx += 256) {
      int c = idx / 130, i = idx - c * 130;
      int l = l0 + i;
      float v = 0.f;
      if ((unsigned)l < 4096u) v = x[(b * 768 + c0 + c) * 4096 + l];
      xs[c * 132 + i] = v;
    }
    for (int idx = tid; idx < 2048; idx += 256) {
      int o = idx & 31, r = idx >> 5;           // r = c*4+k
      ws[r * 32 + o] = w[o * 3072 + c0 * 4 + r];
    }
    __syncthreads();
#pragma unroll
    for (int c = 0; c < 16; c++) {
      const float* wr = ws + c * 128 + og * 4;
      ulonglong2 w0 = *(const ulonglong2*)(wr);
      ulonglong2 w1 = *(const ulonglong2*)(wr + 32);
      ulonglong2 w2 = *(const ulonglong2*)(wr + 64);
      ulonglong2 w3 = *(const ulonglong2*)(wr + 96);
      const float* xr = xs + c * 132 + 2 * tg;
#pragma unroll
      for (int j = 0; j < 2; j++) {
        float2 xa = *(const float2*)(xr + 64 * j);
        float2 xb = *(const float2*)(xr + 64 * j + 2);
        u64 p0 = bcast2(xa.x), p1 = bcast2(xa.y);
        u64 p2 = bcast2(xb.x), p3 = bcast2(xb.y);
        ffma2(acc[0][j], w0.x, p0); ffma2(acc[1][j], w0.y, p0);
        ffma2(acc[0][j], w1.x, p1); ffma2(acc[1][j], w1.y, p1);
        ffma2(acc[0][j], w2.x, p2); ffma2(acc[1][j], w2.y, p2);
        ffma2(acc[0][j], w3.x, p3); ffma2(acc[1][j], w3.y, p3);
      }
    }
  }
#pragma unroll
  for (int p = 0; p < 2; p++) {
    int o = og * 4 + 2 * p;
    float bv0 = bias[o], bv1 = bias[o + 1];
#pragma unroll
    for (int j = 0; j < 2; j++) {
      float2 f = unpack2(acc[p][j]);
      int t = T0 + tg + 32 * j;
      out[(b * 32 + o) * 2048 + t]       = fmaxf(f.x + bv0, 0.f);
      out[(b * 32 + o + 1) * 2048 + t]   = fmaxf(f.y + bv1, 0.f);
    }
  }
}

// =====================================================================
// conv2: (16,32,2048) -> (16,64,1024), k4 s2 p1, bias, ReLU
// grid (32,16).  tile 64o x 32t, full 32-c in smem.
// =====================================================================
__global__ void __launch_bounds__(256) k_conv2(
    const float* __restrict__ in, const float* __restrict__ w,
    const float* __restrict__ bias, float* __restrict__ out) {
  __shared__ __align__(16) float xs[32 * 68];    // 66 valid
  __shared__ __align__(16) float ws[128 * 64];   // [(c*4+k)][o]
  const int b   = blockIdx.y;
  const int T0  = blockIdx.x * 32;
  const int tid = threadIdx.x;
  const int og  = tid & 15;
  const int tg  = tid >> 4;
  const int l0  = 2 * T0 - 1;

  for (int idx = tid; idx < 32 * 66; idx += 256) {
    int c = idx / 66, i = idx - c * 66;
    int l = l0 + i;
    float v = 0.f;
    if ((unsigned)l < 2048u) v = in[(b * 32 + c) * 2048 + l];
    xs[c * 68 + i] = v;
  }
  for (int idx = tid; idx < 8192; idx += 256) {
    int o = idx & 63, r = idx >> 6;             // r = c*4+k
    ws[r * 64 + o] = w[o * 128 + r];
  }
  __syncthreads();

  u64 acc[2][2] = {{0ull, 0ull}, {0ull, 0ull}};
#pragma unroll 4
  for (int c = 0; c < 32; c++) {
    const float* wr = ws + c * 256 + og * 4;
    ulonglong2 w0 = *(const ulonglong2*)(wr);
    ulonglong2 w1 = *(const ulonglong2*)(wr + 64);
    ulonglong2 w2 = *(const ulonglong2*)(wr + 128);
    ulonglong2 w3 = *(const ulonglong2*)(wr + 192);
    const float* xr = xs + c * 68 + 2 * tg;
#pragma unroll
    for (int j = 0; j < 2; j++) {
      float2 xa = *(const float2*)(xr + 32 * j);
      float2 xb = *(const float2*)(xr + 32 * j + 2);
      u64 p0 = bcast2(xa.x), p1 = bcast2(xa.y);
      u64 p2 = bcast2(xb.x), p3 = bcast2(xb.y);
      ffma2(acc[0][j], w0.x, p0); ffma2(acc[1][j], w0.y, p0);
      ffma2(acc[0][j], w1.x, p1); ffma2(acc[1][j], w1.y, p1);
      ffma2(acc[0][j], w2.x, p2); ffma2(acc[1][j], w2.y, p2);
      ffma2(acc[0][j], w3.x, p3); ffma2(acc[1][j], w3.y, p3);
    }
  }
#pragma unroll
  for (int p = 0; p < 2; p++) {
    int o = og * 4 + 2 * p;
    float bv0 = bias[o], bv1 = bias[o + 1];
#pragma unroll
    for (int j = 0; j < 2; j++) {
      float2 f = unpack2(acc[p][j]);
      int t = T0 + tg + 16 * j;
      out[(b * 64 + o) * 1024 + t]     = fmaxf(f.x + bv0, 0.f);
      out[(b * 64 + o + 1) * 1024 + t] = fmaxf(f.y + bv1, 0.f);
    }
  }
}

// =====================================================================
// conv3-type: (16,64,1024) -> (16,64,1024), k3 s1 p1, bias, NO relu
// grid (32,16), tile 32t, c-chunks of 32.
// =====================================================================
__global__ void __launch_bounds__(256) k_conv3(
    const float* __restrict__ in, const float* __restrict__ w,
    const float* __restrict__ bias, float* __restrict__ out) {
  __shared__ __align__(16) float xs[32 * 36];    // 34 valid
  __shared__ __align__(16) float ws[96 * 64];    // [(c*3+k)][o]
  const int b   = blockIdx.y;
  const int T0  = blockIdx.x * 32;
  const int tid = threadIdx.x;
  const int og  = tid & 15;
  const int tg  = tid >> 4;

  u64 acc[2][2] = {{0ull, 0ull}, {0ull, 0ull}};

  for (int c0 = 0; c0 < 64; c0 += 32) {
    __syncthreads();
    for (int idx = tid; idx < 32 * 34; idx += 256) {
      int c = idx / 34, i = idx - c * 34;
      int tt = T0 - 1 + i;
      float v = 0.f;
      if ((unsigned)tt < 1024u) v = in[(b * 64 + c0 + c) * 1024 + tt];
      xs[c * 36 + i] = v;
    }
    for (int idx = tid; idx < 6144; idx += 256) {
      int o = idx & 63, r = idx >> 6;           // r = c*3+k
      ws[r * 64 + o] = w[o * 192 + c0 * 3 + r];
    }
    __syncthreads();
#pragma unroll 4
    for (int c = 0; c < 32; c++) {
      const float* wr = ws + c * 192 + og * 4;
      ulonglong2 w0 = *(const ulonglong2*)(wr);
      ulonglong2 w1 = *(const ulonglong2*)(wr + 64);
      ulonglong2 w2 = *(const ulonglong2*)(wr + 128);
      const float* xr = xs + c * 36 + tg;
#pragma unroll
      for (int j = 0; j < 2; j++) {
        u64 p0 = bcast2(xr[16 * j]);
        u64 p1 = bcast2(xr[16 * j + 1]);
        u64 p2 = bcast2(xr[16 * j + 2]);
        ffma2(acc[0][j], w0.x, p0); ffma2(acc[1][j], w0.y, p0);
        ffma2(acc[0][j], w1.x, p1); ffma2(acc[1][j], w1.y, p1);
        ffma2(acc[0][j], w2.x, p2); ffma2(acc[1][j], w2.y, p2);
      }
    }
  }
#pragma unroll
  for (int p = 0; p < 2; p++) {
    int o = og * 4 + 2 * p;
    float bv0 = bias[o], bv1 = bias[o + 1];
#pragma unroll
    for (int j = 0; j < 2; j++) {
      float2 f = unpack2(acc[p][j]);
      int t = T0 + tg + 16 * j;
      out[(b * 64 + o) * 1024 + t]     = f.x + bv0;
      out[(b * 64 + o + 1) * 1024 + t] = f.y + bv1;
    }
  }
}

// =====================================================================
// fused residual block: out = in + W2 @ relu(conv3(W1, relu(in)))
// grid (32,16), tile 32t.
// =====================================================================
__global__ void __launch_bounds__(256) k_res(
    const float* __restrict__ in, const float* __restrict__ w1,
    const float* __restrict__ w2, float* __restrict__ out, int relu_out) {
  __shared__ __align__(16) float xs[32 * 36];    // relu(in) chunk, 34 valid
  __shared__ __align__(16) float w1s[96 * 32];   // [(c*3+k)][o]
  __shared__ __align__(16) float hs[32 * 33];    // h[32][32] padded
  __shared__ __align__(16) float w2s[32 * 64];   // [c][o]
  const int b   = blockIdx.y;
  const int T0  = blockIdx.x * 32;
  const int tid = threadIdx.x;
  const int og1 = tid & 7;         // stage1: 32 o
  const int tg1 = tid >> 3;        // 32 t
  const int og2 = tid & 15;        // stage2: 64 o
  const int tg2 = tid >> 4;        // 16 groups x 2 t

  for (int idx = tid; idx < 2048; idx += 256) {
    int o = idx & 63, c = idx >> 6;
    w2s[c * 64 + o] = w2[o * 32 + c];
  }

  u64 a1[2] = {0ull, 0ull};
  for (int c0 = 0; c0 < 64; c0 += 32) {
    __syncthreads();
    for (int idx = tid; idx < 32 * 34; idx += 256) {
      int c = idx / 34, i = idx - c * 34;
      int tt = T0 - 1 + i;
      float v = 0.f;
      if ((unsigned)tt < 1024u) v = in[(b * 64 + c0 + c) * 1024 + tt];
      xs[c * 36 + i] = fmaxf(v, 0.f);
    }
    for (int idx = tid; idx < 3072; idx += 256) {
      int o = idx & 31, r = idx >> 5;           // r = c*3+k
      w1s[r * 32 + o] = w1[o * 192 + c0 * 3 + r];
    }
    __syncthreads();
#pragma unroll 4
    for (int c = 0; c < 32; c++) {
      const float* wr = w1s + c * 96 + og1 * 4;
      ulonglong2 w0 = *(const ulonglong2*)(wr);
      ulonglong2 wv1 = *(const ulonglong2*)(wr + 32);
      ulonglong2 wv2 = *(const ulonglong2*)(wr + 64);
      const float* xr = xs + c * 36 + tg1;
      u64 p0 = bcast2(xr[0]), p1 = bcast2(xr[1]), p2 = bcast2(xr[2]);
      ffma2(a1[0], w0.x, p0);  ffma2(a1[1], w0.y, p0);
      ffma2(a1[0], wv1.x, p1); ffma2(a1[1], wv1.y, p1);
      ffma2(a1[0], wv2.x, p2); ffma2(a1[1], wv2.y, p2);
    }
  }
  __syncthreads();
#pragma unroll
  for (int p = 0; p < 2; p++) {
    float2 f = unpack2(a1[p]);
    hs[(og1 * 4 + 2 * p) * 33 + tg1]     = fmaxf(f.x, 0.f);
    hs[(og1 * 4 + 2 * p + 1) * 33 + tg1] = fmaxf(f.y, 0.f);
  }
  __syncthreads();

  u64 a2[2][2] = {{0ull, 0ull}, {0ull, 0ull}};
#pragma unroll 4
  for (int c = 0; c < 32; c++) {
    ulonglong2 wp = *(const ulonglong2*)(w2s + c * 64 + og2 * 4);
    const float* hr = hs + c * 33 + tg2;
#pragma unroll
    for (int j = 0; j < 2; j++) {
      u64 ph = bcast2(hr[16 * j]);
      ffma2(a2[0][j], wp.x, ph); ffma2(a2[1][j], wp.y, ph);
    }
  }
#pragma unroll
  for (int p = 0; p < 2; p++) {
    int o = og2 * 4 + 2 * p;
#pragma unroll
    for (int j = 0; j < 2; j++) {
      float2 f = unpack2(a2[p][j]);
      int t = T0 + tg2 + 16 * j;
      float r0 = in[(b * 64 + o) * 1024 + t] + f.x;
      float r1 = in[(b * 64 + o + 1) * 1024 + t] + f.y;
      if (relu_out) { r0 = fmaxf(r0, 0.f); r1 = fmaxf(r1, 0.f); }
      out[(b * 64 + o) * 1024 + t]     = r0;
      out[(b * 64 + o + 1) * 1024 + t] = r1;
    }
  }
}

// =====================================================================
// prevq: 1x1 conv 64->64 + bias.  grid (32,16), tile 32t.
// =====================================================================
__global__ void __launch_bounds__(256) k_prevq(
    const float* __restrict__ in, const float* __restrict__ w,
    const float* __restrict__ bias, float* __restrict__ out) {
  __shared__ __align__(16) float ins[64 * 34];
  __shared__ __align__(16) float ws[64 * 64];    // [c][o]
  const int b   = blockIdx.y;
  const int T0  = blockIdx.x * 32;
  const int tid = threadIdx.x;
  const int og  = tid & 15;
  const int tg  = tid >> 4;

  for (int idx = tid; idx < 2048; idx += 256) {
    int c = idx >> 5, t = idx & 31;
    ins[c * 34 + t] = in[(b * 64 + c) * 1024 + T0 + t];
  }
  for (int idx = tid; idx < 4096; idx += 256) {
    int o = idx & 63, c = idx >> 6;
    ws[c * 64 + o] = w[o * 64 + c];
  }
  __syncthreads();

  u64 acc[2][2] = {{0ull, 0ull}, {0ull, 0ull}};
#pragma unroll 4
  for (int c = 0; c < 64; c++) {
    ulonglong2 wp = *(const ulonglong2*)(ws + c * 64 + og * 4);
    const float* xr = ins + c * 34 + tg;
#pragma unroll
    for (int j = 0; j < 2; j++) {
      u64 px = bcast2(xr[16 * j]);
      ffma2(acc[0][j], wp.x, px); ffma2(acc[1][j], wp.y, px);
    }
  }
#pragma unroll
  for (int p = 0; p < 2; p++) {
    int o = og * 4 + 2 * p;
    float bv0 = bias[o], bv1 = bias[o + 1];
#pragma unroll
    for (int j = 0; j < 2; j++) {
      float2 f = unpack2(acc[p][j]);
      int t = T0 + tg + 16 * j;
      out[(b * 64 + o) * 1024 + t]     = f.x + bv0;
      out[(b * 64 + o + 1) * 1024 + t] = f.y + bv1;
    }
  }
}

// =====================================================================
// VQ: e2 precompute + per-token argmin (4-way code split) + ST write
// =====================================================================
__global__ void k_e2(const float* __restrict__ emb) {
  int i = threadIdx.x;              // 512 threads
  float s = 0.f;
#pragma unroll 8
  for (int c = 0; c < 64; c++) {
    float e = emb[i * 64 + c];
    s += e * e;
  }
  g_e2[i] = s;
}

// block = 256 threads = 64 tokens x 4 splits; grid 256
__global__ void __launch_bounds__(256) k_vq(
    const float* __restrict__ z, const float* __restrict__ emb,
    float* __restrict__ q) {
  __shared__ __align__(16) float es[64 * 64];    // 64-code chunk
  __shared__ float e2s[64];
  const int tid = threadIdx.x;
  const int s   = tid & 3;                       // split id
  const int tl  = tid >> 2;                      // token within block
  const int token = blockIdx.x * 64 + tl;
  const int b = token >> 10;
  const int t = token & 1023;

  // z packed as 32 f32x2 pairs (dims 2c, 2c+1)
  u64 zp[32];
#pragma unroll
  for (int c = 0; c < 32; c++) {
    float z0 = z[(b * 64 + 2 * c) * 1024 + t];
    float z1 = z[(b * 64 + 2 * c + 1) * 1024 + t];
    zp[c] = pack2(z0, z1);
  }

  float bs = 3.4e38f;
  int bi = 0;
  for (int cb = 0; cb < 512; cb += 64) {
    __syncthreads();
    for (int idx = tid; idx < 4096; idx += 256) es[idx] = emb[cb * 64 + idx];
    if (tid < 64) e2s[tid] = g_e2[cb + tid];
    __syncthreads();
#pragma unroll 2
    for (int cc = 0; cc < 16; cc++) {
      int code = s * 16 + cc;
      const ulonglong2* ep = (const ulonglong2*)(es + code * 64);
      u64 d0 = 0ull, d1 = 0ull;
#pragma unroll
      for (int qq = 0; qq < 16; qq++) {
        ulonglong2 e = ep[qq];
        ffma2(d0, zp[2 * qq], e.x);
        ffma2(d1, zp[2 * qq + 1], e.y);
      }
      float2 f0 = unpack2(d0), f1 = unpack2(d1);
      float dot = (f0.x + f0.y) + (f1.x + f1.y);
      float score = e2s[code] - 2.f * dot;
      if (score < bs) { bs = score; bi = cb + code; }
    }
  }
  // combine 4 splits (lanes tid^1, tid^2); tie -> lower index (argmin-first)
#pragma unroll
  for (int m = 1; m <= 2; m <<= 1) {
    float os = __shfl_xor_sync(0xffffffffu, bs, m);
    int   oi = __shfl_xor_sync(0xffffffffu, bi, m);
    if (os < bs || (os == bs && oi < bi)) { bs = os; bi = oi; }
  }
  if (s == 0) {
    const float* eb = emb + bi * 64;
#pragma unroll
    for (int c = 0; c < 32; c++) {
      float2 zv = unpack2(zp[c]);
      q[(b * 64 + 2 * c) * 1024 + t]     = zv.x + (eb[2 * c] - zv.x);
      q[(b * 64 + 2 * c + 1) * 1024 + t] = zv.y + (eb[2 * c + 1] - zv.y);
    }
  }
}

// =====================================================================
// dect1: ConvTranspose 64->32 k4 s2 p1 + bias + ReLU
// (16,64,1024) -> (16,32,2048).  grid (32,16), tile 32 s -> 64 t.
// =====================================================================
__global__ void __launch_bounds__(256) k_dect1(
    const float* __restrict__ in, const float* __restrict__ w,
    const float* __restrict__ bias, float* __restrict__ out) {
  __shared__ __align__(16) float xs[32 * 36];    // 34 valid
  __shared__ __align__(16) float ws[128 * 32];   // [(c*4+k)][o]
  const int b   = blockIdx.y;
  const int S0  = blockIdx.x * 32;
  const int tid = threadIdx.x;
  const int og  = tid & 7;
  const int sg  = tid >> 3;

  u64 ae[2] = {0ull, 0ull}, ao[2] = {0ull, 0ull};

  for (int c0 = 0; c0 < 64; c0 += 32) {
    __syncthreads();
    for (int idx = tid; idx < 32 * 34; idx += 256) {
      int c = idx / 34, i = idx - c * 34;
      int ss = S0 - 1 + i;
      float v = 0.f;
      if ((unsigned)ss < 1024u) v = in[(b * 64 + c0 + c) * 1024 + ss];
      xs[c * 36 + i] = v;
    }
    for (int idx = tid; idx < 4096; idx += 256) {
      int o = idx & 31, r = idx >> 5;           // r = c*4+k
      ws[r * 32 + o] = w[(c0 + (r >> 2)) * 128 + o * 4 + (r & 3)];
    }
    __syncthreads();
#pragma unroll 4
    for (int c = 0; c < 32; c++) {
      const float* wr = ws + c * 128 + og * 4;
      ulonglong2 w0 = *(const ulonglong2*)(wr);
      ulonglong2 w1 = *(const ulonglong2*)(wr + 32);
      ulonglong2 w2 = *(const ulonglong2*)(wr + 64);
      ulonglong2 w3 = *(const ulonglong2*)(wr + 96);
      const float* xr = xs + c * 36 + sg;
      u64 pm = bcast2(xr[0]), pc = bcast2(xr[1]), pp = bcast2(xr[2]);
      ffma2(ae[0], w1.x, pc); ffma2(ae[1], w1.y, pc);
      ffma2(ae[0], w3.x, pm); ffma2(ae[1], w3.y, pm);
      ffma2(ao[0], w0.x, pp); ffma2(ao[1], w0.y, pp);
      ffma2(ao[0], w2.x, pc); ffma2(ao[1], w2.y, pc);
    }
  }
#pragma unroll
  for (int p = 0; p < 2; p++) {
    int o = og * 4 + 2 * p;
    float bv0 = bias[o], bv1 = bias[o + 1];
    float2 fe = unpack2(ae[p]), fo = unpack2(ao[p]);
    int te = 2 * (S0 + sg);
    out[(b * 32 + o) * 2048 + te]         = fmaxf(fe.x + bv0, 0.f);
    out[(b * 32 + o) * 2048 + te + 1]     = fmaxf(fo.x + bv0, 0.f);
    out[(b * 32 + o + 1) * 2048 + te]     = fmaxf(fe.y + bv1, 0.f);
    out[(b * 32 + o + 1) * 2048 + te + 1] = fmaxf(fo.y + bv1, 0.f);
  }
}

// =====================================================================
// dect2: ConvTranspose 32->64 k4 s2 p1 + bias (final output)
// (16,32,2048) -> (16,64,4096).  grid (32,16), tile 64 s -> 128 t.
// =====================================================================
__global__ void __launch_bounds__(256) k_dect2(
    const float* __restrict__ in, const float* __restrict__ w,
    const float* __restrict__ bias, float* __restrict__ out) {
  __shared__ __align__(16) float xs[32 * 68];    // 66 valid
  __shared__ __align__(16) float ws[128 * 64];   // [(c*4+k)][o]
  const int b   = blockIdx.y;
  const int S0  = blockIdx.x * 64;
  const int tid = threadIdx.x;
  const int og  = tid & 15;
  const int sg  = tid >> 4;

  for (int idx = tid; idx < 32 * 66; idx += 256) {
    int c = idx / 66, i = idx - c * 66;
    int ss = S0 - 1 + i;
    float v = 0.f;
    if ((unsigned)ss < 2048u) v = in[(b * 32 + c) * 2048 + ss];
    xs[c * 68 + i] = v;
  }
  for (int idx = tid; idx < 8192; idx += 256) {
    int o = idx & 63, r = idx >> 6;             // r = c*4+k
    ws[r * 64 + o] = w[(r >> 2) * 256 + o * 4 + (r & 3)];
  }
  __syncthreads();

  u64 ae[2][4], ao[2][4];
#pragma unroll
  for (int p = 0; p < 2; p++)
#pragma unroll
    for (int j = 0; j < 4; j++) { ae[p][j] = 0ull; ao[p][j] = 0ull; }

#pragma unroll 2
  for (int c = 0; c < 32; c++) {
    const float* wr = ws + c * 256 + og * 4;
    ulonglong2 w0 = *(const ulonglong2*)(wr);
    ulonglong2 w1 = *(const ulonglong2*)(wr + 64);
    ulonglong2 w2 = *(const ulonglong2*)(wr + 128);
    ulonglong2 w3 = *(const ulonglong2*)(wr + 192);
    const float* xr = xs + c * 68 + sg;
#pragma unroll
    for (int j = 0; j < 4; j++) {
      u64 pm = bcast2(xr[16 * j]);
      u64 pc = bcast2(xr[16 * j + 1]);
      u64 pp = bcast2(xr[16 * j + 2]);
      ffma2(ae[0][j], w1.x, pc); ffma2(ae[1][j], w1.y, pc);
      ffma2(ae[0][j], w3.x, pm); ffma2(ae[1][j], w3.y, pm);
      ffma2(ao[0][j], w0.x, pp); ffma2(ao[1][j], w0.y, pp);
      ffma2(ao[0][j], w2.x, pc); ffma2(ao[1][j], w2.y, pc);
    }
  }
#pragma unroll
  for (int p = 0; p < 2; p++) {
    int o = og * 4 + 2 * p;
    float bv0 = bias[o], bv1 = bias[o + 1];
#pragma unroll
    for (int j = 0; j < 4; j++) {
      float2 fe = unpack2(ae[p][j]), fo = unpack2(ao[p][j]);
      int te = 2 * (S0 + sg + 16 * j);
      out[(b * 64 + o) * 4096 + te]         = fe.x + bv0;
      out[(b * 64 + o) * 4096 + te + 1]     = fo.x + bv0;
      out[(b * 64 + o + 1) * 4096 + te]     = fe.y + bv1;
      out[(b * 64 + o + 1) * 4096 + te + 1] = fo.y + bv1;
    }
  }
}

// =====================================================================
extern "C" void kernel_launch(void* const* d_in, const int* in_sizes, int n_in,
                              void* d_out, int out_size) {
  const float* x        = (const float*)d_in[0];
  const float* enc_w1   = (const float*)d_in[1];
  const float* enc_b1   = (const float*)d_in[2];
  const float* enc_w2   = (const float*)d_in[3];
  const float* enc_b2   = (const float*)d_in[4];
  const float* enc_w3   = (const float*)d_in[5];
  const float* enc_b3   = (const float*)d_in[6];
  const float* enc_r0w1 = (const float*)d_in[7];
  const float* enc_r0w2 = (const float*)d_in[8];
  const float* enc_r1w1 = (const float*)d_in[9];
  const float* enc_r1w2 = (const float*)d_in[10];
  const float* prevq_w  = (const float*)d_in[11];
  const float* prevq_b  = (const float*)d_in[12];
  const float* emb      = (const float*)d_in[13];
  const float* dec_w1   = (const float*)d_in[14];
  const float* dec_b1   = (const float*)d_in[15];
  const float* dec_r0w1 = (const float*)d_in[16];
  const float* dec_r0w2 = (const float*)d_in[17];
  const float* dec_r1w1 = (const float*)d_in[18];
  const float* dec_r1w2 = (const float*)d_in[19];
  const float* dect1_w  = (const float*)d_in[20];
  const float* dect1_b  = (const float*)d_in[21];
  const float* dect2_w  = (const float*)d_in[22];
  const float* dect2_b  = (const float*)d_in[23];
  float* out = (float*)d_out;

  float *A, *B;
  cudaGetSymbolAddress((void**)&A, g_bufA);
  cudaGetSymbolAddress((void**)&B, g_bufB);

  dim3 blk(256);
  k_e2<<<1, 512>>>(emb);
  k_conv1<<<dim3(32, BATCH), blk>>>(x, enc_w1, enc_b1, A);
  k_conv2<<<dim3(32, BATCH), blk>>>(A, enc_w2, enc_b2, B);
  k_conv3<<<dim3(32, BATCH), blk>>>(B, enc_w3, enc_b3, A);
  k_res  <<<dim3(32, BATCH), blk>>>(A, enc_r0w1, enc_r0w2, B, 0);
  k_res  <<<dim3(32, BATCH), blk>>>(B, enc_r1w1, enc_r1w2, A, 1);
  k_prevq<<<dim3(32, BATCH), blk>>>(A, prevq_w, prevq_b, B);   // z in B
  k_vq   <<<256, 256>>>(B, emb, A);                            // q in A
  k_conv3<<<dim3(32, BATCH), blk>>>(A, dec_w1, dec_b1, B);
  k_res  <<<dim3(32, BATCH), blk>>>(B, dec_r0w1, dec_r0w2, A, 0);
  k_res  <<<dim3(32, BATCH), blk>>>(A, dec_r1w1, dec_r1w2, B, 1);
  k_dect1<<<dim3(32, BATCH), blk>>>(B, dect1_w, dect1_b, A);
  k_dect2<<<dim3(32, BATCH), blk>>>(A, dect2_w, dect2_b, out);
  (void)in_sizes; (void)n_in; (void)out_size;
}